// round 3
// baseline (speedup 1.0000x reference)
#include <cuda_runtime.h>

// SpatialGradientLoss3D = mean |sobel3d(pred - target)| over 3 axes.
// R3: full-W tiles (8 rows x 128), vectorized float4 LDG/STS/LDS,
// shfl-based w-convolution at load time (stage1), h-combine from smem
// (stage2), fully unrolled 18-plane pipelined z-march, 1 sync/plane.
// Shapes fixed: (B=4, C=4, D=64, H=128, W=128), fp32, out = 1 float.

#define D_DIM 64
#define H_DIM 128
#define W_DIM 128
#define HW    (H_DIM * W_DIM)
#define HW4   (HW / 4)          // 4096 float4 per plane
#define W4    (W_DIM / 4)       // 32 float4 per row
#define BC_DIM 16
#define TH 8                    // output rows per block
#define PR (TH + 2)             // 10 plane rows (h halo)
#define ZC 16                   // z outputs per block
#define NPLANES (ZC + 2)        // 18 planes touched

__global__ void sg3d_zero_out(float* out) { out[0] = 0.0f; }

__device__ __forceinline__ float4 f4zero() { return make_float4(0.f, 0.f, 0.f, 0.f); }

// stage1: w-direction separable partials for one row-slot, store to smem.
// ws = [1,2,1]*e along w ; wd = [-1,0,1]*e along w. Warp-wide (one row).
__device__ __forceinline__ void stage1(float4 p, float4 t, int lane,
                                       float4* wsrow, float4* wdrow) {
    float e0 = p.x - t.x, e1 = p.y - t.y, e2 = p.z - t.z, e3 = p.w - t.w;
    float eL = __shfl_up_sync(0xffffffffu, e3, 1);
    float eR = __shfl_down_sync(0xffffffffu, e0, 1);
    if (lane == 0)  eL = 0.f;   // W zero-pad
    if (lane == 31) eR = 0.f;
    float4 ws, wd;
    ws.x = eL + 2.f * e0 + e1;
    ws.y = e0 + 2.f * e1 + e2;
    ws.z = e1 + 2.f * e2 + e3;
    ws.w = e2 + 2.f * e3 + eR;
    wd.x = e1 - eL;
    wd.y = e2 - e0;
    wd.z = e3 - e1;
    wd.w = eR - e2;
    wsrow[lane] = ws;
    wdrow[lane] = wd;
}

__global__ __launch_bounds__(256, 3)
void sg3d_loss_kernel(const float4* __restrict__ pred,
                      const float4* __restrict__ tgt,
                      float* __restrict__ out) {
    const int tid  = threadIdx.x;
    const int lane = tid & 31;
    const int warp = tid >> 5;          // 0..7 = output row

    const int h0 = blockIdx.x * TH;
    const int bc = blockIdx.y;
    const int z0 = blockIdx.z * ZC;

    const size_t base4 = (size_t)bc * D_DIM * HW4;
    const float4* P = pred + base4;
    const float4* T = tgt + base4;

    __shared__ float4 sws[2][PR][W4];
    __shared__ float4 swd[2][PR][W4];

    // slot0: plane row = warp (all warps); slot1: plane row = warp+8 (warps 0,1)
    const int r0 = warp;
    const int r1 = warp + 8;
    const bool has1 = (tid < 64);
    const int gh0 = h0 - 1 + r0;
    const int gh1 = h0 - 1 + r1;
    const bool v0 = (unsigned)gh0 < (unsigned)H_DIM;
    const bool v1 = has1 && ((unsigned)gh1 < (unsigned)H_DIM);
    const int off0 = gh0 * W4 + lane;   // float4 index within a plane
    const int off1 = gh1 * W4 + lane;

    float4 ss[3], ds[3], sd[3];
    float4 acc = f4zero();

    // prologue: load plane z0-1 into regs
    float4 a0 = f4zero(), b0 = f4zero(), a1 = f4zero(), b1 = f4zero();
    if (z0 > 0) {
        const int pb = (z0 - 1) * HW4;
        if (v0) { a0 = P[pb + off0]; b0 = T[pb + off0]; }
        if (v1) { a1 = P[pb + off1]; b1 = T[pb + off1]; }
    }

#pragma unroll
    for (int i = 0; i < NPLANES; ++i) {
        const int buf = i & 1;

        // stage1 + store for plane z0-1+i (values already in regs)
        stage1(a0, b0, lane, sws[buf][r0], swd[buf][r0]);
        if (has1) stage1(a1, b1, lane, sws[buf][r1], swd[buf][r1]);

        // prefetch next plane (consumed next iteration)
        if (i < NPLANES - 1) {
            const int pz = z0 + i;
            const bool zv = pz < D_DIM;   // pz >= 0 always here
            const int pb = pz * HW4;
            a0 = f4zero(); b0 = f4zero(); a1 = f4zero(); b1 = f4zero();
            if (zv && v0) { a0 = P[pb + off0]; b0 = T[pb + off0]; }
            if (zv && v1) { a1 = P[pb + off1]; b1 = T[pb + off1]; }
        }

        __syncthreads();

        // stage2: h-combine for this plane into rotating slot (compile-time idx)
        const int s = i % 3;
        {
            float4 m = sws[buf][warp][lane];
            float4 c = sws[buf][warp + 1][lane];
            float4 p = sws[buf][warp + 2][lane];
            ss[s].x = m.x + 2.f * c.x + p.x;  ds[s].x = p.x - m.x;
            ss[s].y = m.y + 2.f * c.y + p.y;  ds[s].y = p.y - m.y;
            ss[s].z = m.z + 2.f * c.z + p.z;  ds[s].z = p.z - m.z;
            ss[s].w = m.w + 2.f * c.w + p.w;  ds[s].w = p.w - m.w;
            float4 dm = swd[buf][warp][lane];
            float4 dc = swd[buf][warp + 1][lane];
            float4 dp = swd[buf][warp + 2][lane];
            sd[s].x = dm.x + 2.f * dc.x + dp.x;
            sd[s].y = dm.y + 2.f * dc.y + dp.y;
            sd[s].z = dm.z + 2.f * dc.z + dp.z;
            sd[s].w = dm.w + 2.f * dc.w + dp.w;
        }

        // combine: output plane z0 + (i-2) uses slots i-2 (m1), i-1 (0), i (p1)
        if (i >= 2) {
            const int sm = (i - 2) % 3, s0 = (i - 1) % 3, sp = s;
            float4 gd, gh, gw;
            gd.x = ss[sp].x - ss[sm].x;  gd.y = ss[sp].y - ss[sm].y;
            gd.z = ss[sp].z - ss[sm].z;  gd.w = ss[sp].w - ss[sm].w;
            gh.x = ds[sm].x + 2.f * ds[s0].x + ds[sp].x;
            gh.y = ds[sm].y + 2.f * ds[s0].y + ds[sp].y;
            gh.z = ds[sm].z + 2.f * ds[s0].z + ds[sp].z;
            gh.w = ds[sm].w + 2.f * ds[s0].w + ds[sp].w;
            gw.x = sd[sm].x + 2.f * sd[s0].x + sd[sp].x;
            gw.y = sd[sm].y + 2.f * sd[s0].y + sd[sp].y;
            gw.z = sd[sm].z + 2.f * sd[s0].z + sd[sp].z;
            gw.w = sd[sm].w + 2.f * sd[s0].w + sd[sp].w;
            acc.x += fabsf(gd.x); acc.x += fabsf(gh.x); acc.x += fabsf(gw.x);
            acc.y += fabsf(gd.y); acc.y += fabsf(gh.y); acc.y += fabsf(gw.y);
            acc.z += fabsf(gd.z); acc.z += fabsf(gh.z); acc.z += fabsf(gw.z);
            acc.w += fabsf(gd.w); acc.w += fabsf(gh.w); acc.w += fabsf(gw.w);
        }
    }

    // reduction
    float a = (acc.x + acc.y) + (acc.z + acc.w);
#pragma unroll
    for (int off = 16; off > 0; off >>= 1)
        a += __shfl_down_sync(0xffffffffu, a, off);

    __shared__ float wsum[8];
    if (lane == 0) wsum[warp] = a;
    __syncthreads();
    if (warp == 0) {
        float v = (lane < 8) ? wsum[lane] : 0.0f;
#pragma unroll
        for (int off = 4; off > 0; off >>= 1)
            v += __shfl_down_sync(0xffffffffu, v, off);
        if (lane == 0)
            atomicAdd(out, v * (1.0f / (3.0f * 16.0f * 64.0f * 128.0f * 128.0f)));
    }
}

extern "C" void kernel_launch(void* const* d_in, const int* in_sizes, int n_in,
                              void* d_out, int out_size) {
    const float4* pred = (const float4*)d_in[0];
    const float4* tgt  = (const float4*)d_in[1];
    float* out = (float*)d_out;

    sg3d_zero_out<<<1, 1>>>(out);

    dim3 grid(H_DIM / TH, BC_DIM, D_DIM / ZC);   // 16 x 16 x 4 = 1024 blocks
    sg3d_loss_kernel<<<grid, 256>>>(pred, tgt, out);
}

// round 4
// speedup vs baseline: 1.4310x; 1.4310x over previous
#include <cuda_runtime.h>
#include <cstdint>

// SpatialGradientLoss3D = mean |sobel3d(pred - target)| over 3 axes.
// R4: cp.async (LDGSTS) 3-stage smem ring of RAW p/t planes, issued 2 planes
// ahead (no LDG->reg->STS chain). Consumer per plane: 6x LDS.128, diff,
// w-conv via shfl, h-combine in regs, 3-slot z rotation. 1 sync/plane.
// Shapes fixed: (B=4, C=4, D=64, H=128, W=128), fp32, out = 1 float.

#define D_DIM 64
#define H_DIM 128
#define W_DIM 128
#define HW    (H_DIM * W_DIM)
#define BC_DIM 16
#define TH 8                    // output rows per block
#define PR (TH + 2)             // 10 plane rows incl. h halo
#define ZC 16                   // z outputs per block
#define NP (ZC + 2)             // 18 planes touched
#define NSTAGE 3
#define PLANE_F4 (2 * PR * 32)  // 640 float4 per stage (P then T)
#define STAGE_BYTES (PLANE_F4 * 16)   // 10240

__global__ void sg3d_zero_out(float* out) { out[0] = 0.0f; }

__device__ __forceinline__ void cpasync16(uint32_t dst, const float* src, int sz) {
    asm volatile("cp.async.cg.shared.global [%0], [%1], 16, %2;\n"
                 :: "r"(dst), "l"(src), "r"(sz) : "memory");
}
__device__ __forceinline__ void cp_commit() {
    asm volatile("cp.async.commit_group;\n" ::: "memory");
}
__device__ __forceinline__ void cp_wait1() {
    asm volatile("cp.async.wait_group 1;\n" ::: "memory");
}

__shared__ float4 sbuf[NSTAGE][PLANE_F4];
__shared__ float wsum_sm[8];

// Consume one plane from stage S: produce ss/ds/sd slot S for this thread's
// 4 output columns (lane) at output row = warp.
template<int S>
__device__ __forceinline__ void plane_consume(int warp, int lane,
                                              float4* ss, float4* ds, float4* sd) {
    const float4* sb = &sbuf[S][0];
    float ws[3][4], wd[3][4];
#pragma unroll
    for (int dr = 0; dr < 3; ++dr) {
        float4 p = sb[(warp + dr) * 32 + lane];
        float4 t = sb[PR * 32 + (warp + dr) * 32 + lane];
        float e0 = p.x - t.x, e1 = p.y - t.y, e2 = p.z - t.z, e3 = p.w - t.w;
        float eL = __shfl_up_sync(0xffffffffu, e3, 1);
        float eR = __shfl_down_sync(0xffffffffu, e0, 1);
        if (lane == 0)  eL = 0.f;
        if (lane == 31) eR = 0.f;
        ws[dr][0] = eL + 2.f * e0 + e1;
        ws[dr][1] = e0 + 2.f * e1 + e2;
        ws[dr][2] = e1 + 2.f * e2 + e3;
        ws[dr][3] = e2 + 2.f * e3 + eR;
        wd[dr][0] = e1 - eL;
        wd[dr][1] = e2 - e0;
        wd[dr][2] = e3 - e1;
        wd[dr][3] = eR - e2;
    }
    float* ssp = (float*)&ss[S];
    float* dsp = (float*)&ds[S];
    float* sdp = (float*)&sd[S];
#pragma unroll
    for (int i = 0; i < 4; ++i) {
        ssp[i] = ws[0][i] + 2.f * ws[1][i] + ws[2][i];
        dsp[i] = ws[2][i] - ws[0][i];
        sdp[i] = wd[0][i] + 2.f * wd[1][i] + wd[2][i];
    }
}

template<int SP>
__device__ __forceinline__ void z_combine(const float4* ss, const float4* ds,
                                          const float4* sd, float4& acc) {
    constexpr int SM = (SP + 1) % 3;
    constexpr int S0 = (SP + 2) % 3;
    const float* sm_s = (const float*)&ss[SM];
    const float* sp_s = (const float*)&ss[SP];
    const float* dm = (const float*)&ds[SM];
    const float* d0 = (const float*)&ds[S0];
    const float* dp = (const float*)&ds[SP];
    const float* wm = (const float*)&sd[SM];
    const float* w0 = (const float*)&sd[S0];
    const float* wp = (const float*)&sd[SP];
    float* a = (float*)&acc;
#pragma unroll
    for (int i = 0; i < 4; ++i) {
        float gd = sp_s[i] - sm_s[i];
        float gh = dm[i] + 2.f * d0[i] + dp[i];
        float gw = wm[i] + 2.f * w0[i] + wp[i];
        a[i] += fabsf(gd) + fabsf(gh) + fabsf(gw);
    }
}

__global__ __launch_bounds__(256, 3)
void sg3d_loss_kernel(const float* __restrict__ pred,
                      const float* __restrict__ tgt,
                      float* __restrict__ out) {
    const int tid  = threadIdx.x;
    const int lane = tid & 31;
    const int warp = tid >> 5;          // 0..7 = output row

    const int h0 = blockIdx.x * TH;
    const int bc = blockIdx.y;
    const int z0 = blockIdx.z * ZC;

    const size_t base = (size_t)bc * D_DIM * HW;
    const float* P = pred + base;
    const float* T = tgt + base;

    uint32_t smem_base;
    asm("{ .reg .u64 t; cvta.to.shared.u64 t, %1; cvt.u32.u64 %0, t; }"
        : "=r"(smem_base) : "l"((const void*)&sbuf[0][0]));

    // ---- per-slot cp.async params (hoisted) ----
    // idx k over [0,640): idx<320 -> P plane rows, else T. slot k: tid+256k.
    const float* gp[3];
    uint32_t saddr[3];
    int rowok[3], active[3];
#pragma unroll
    for (int k = 0; k < 3; ++k) {
        int idx = tid + 256 * k;
        active[k] = idx < PLANE_F4;
        int a   = idx >= PR * 32;
        int rel = idx - a * PR * 32;
        int row = rel >> 5;
        int c4  = rel & 31;
        int gh  = h0 - 1 + row;
        rowok[k] = (unsigned)gh < (unsigned)H_DIM;
        int soff = (rowok[k] ? gh : 0) * W_DIM + c4 * 4;
        gp[k] = (a ? T : P) + soff;
        saddr[k] = smem_base + (uint32_t)idx * 16u;
    }

    // issue plane j (tile plane index, global z = z0-1+j) into given stage
#define ISSUE_PLANE(J, STAGE)                                                 \
    do {                                                                      \
        int gz_ = z0 - 1 + (J);                                               \
        int zok_ = (unsigned)gz_ < (unsigned)D_DIM;                           \
        int gzc_ = zok_ ? gz_ : 0;                                            \
        _Pragma("unroll")                                                     \
        for (int k = 0; k < 3; ++k) {                                         \
            if (active[k]) {                                                  \
                int sz_ = (rowok[k] & zok_) ? 16 : 0;                         \
                cpasync16(saddr[k] + (STAGE) * STAGE_BYTES,                   \
                          gp[k] + (size_t)gzc_ * HW, sz_);                    \
            }                                                                 \
        }                                                                     \
    } while (0)

    float4 ss[3], ds[3], sd[3];
    float4 acc = make_float4(0.f, 0.f, 0.f, 0.f);

    // prologue: planes 0,1 -> stages 0,1
    ISSUE_PLANE(0, 0); cp_commit();
    ISSUE_PLANE(1, 1); cp_commit();

#define STEP(U, ii)                                                           \
    do {                                                                      \
        const int i_ = (ii) + (U);                                            \
        cp_wait1();                                                           \
        __syncthreads();                                                      \
        const int j_ = i_ + 2;                                                \
        if (j_ < NP) ISSUE_PLANE(j_, ((U) + 2) % 3);                          \
        cp_commit();                                                          \
        plane_consume<(U)>(warp, lane, ss, ds, sd);                           \
        if (i_ >= 2) z_combine<(U)>(ss, ds, sd, acc);                         \
    } while (0)

    for (int ii = 0; ii < NP; ii += 3) {
        STEP(0, ii);
        STEP(1, ii);
        STEP(2, ii);
    }

    // ---- reduction ----
    float a = (acc.x + acc.y) + (acc.z + acc.w);
#pragma unroll
    for (int off = 16; off > 0; off >>= 1)
        a += __shfl_down_sync(0xffffffffu, a, off);

    if (lane == 0) wsum_sm[warp] = a;
    __syncthreads();
    if (warp == 0) {
        float v = (lane < 8) ? wsum_sm[lane] : 0.0f;
#pragma unroll
        for (int off = 4; off > 0; off >>= 1)
            v += __shfl_down_sync(0xffffffffu, v, off);
        if (lane == 0)
            atomicAdd(out, v * (1.0f / (3.0f * 16.0f * 64.0f * 128.0f * 128.0f)));
    }
}

extern "C" void kernel_launch(void* const* d_in, const int* in_sizes, int n_in,
                              void* d_out, int out_size) {
    const float* pred = (const float*)d_in[0];
    const float* tgt  = (const float*)d_in[1];
    float* out = (float*)d_out;

    sg3d_zero_out<<<1, 1>>>(out);

    dim3 grid(H_DIM / TH, BC_DIM, D_DIM / ZC);   // 16 x 16 x 4 = 1024 blocks
    sg3d_loss_kernel<<<grid, 256>>>(pred, tgt, out);
}